// round 2
// baseline (speedup 1.0000x reference)
#include <cuda_runtime.h>
#include <math.h>

#define NB   512
#define CIN  156
#define COUT 50
#define TT   325
#define THREADS 256

#define CCHUNK 26
#define NCHUNK 6
#define NPAIR  13
#define XROW2F 852          // floats per interleaved pair-row (2*(100 pad + 325) + 2 spare)
#define PAD2   100          // left zero pad, in float2 units

#define CONV_TG   19
#define CONV_TILE 18
#define CONV_ACT  (NPAIR*CONV_TG)   // 247

#define OG 5
#define GEMM_ACT 205

// smem float offsets
#define OFF_EPS 0                      // ull eps2[100] = 200 floats
#define OFF_PSP 200                    // psp[156][325]
#define OFF_XI2 42452                  // staging, overlaps psp rows 130..155
#define OFF_WS  53532                  // W chunk [26][52]
#define SMEM_FLOATS 54884              // 219,536 B

#define OFF_Y   200                    // y[50][YSTR], overlays dead psp
#define YSTR    327
#define OFF_S   (OFF_Y + COUT*YSTR)    // 16550

typedef unsigned long long ull;

__device__ __forceinline__ ull pack2(float lo, float hi) {
    ull r; asm("mov.b64 %0, {%1, %2};" : "=l"(r) : "f"(lo), "f"(hi)); return r;
}
__device__ __forceinline__ void unpack2(ull v, float &lo, float &hi) {
    asm("mov.b64 {%0, %1}, %2;" : "=f"(lo), "=f"(hi) : "l"(v));
}
__device__ __forceinline__ void fma2(ull &d, ull a, ull b) {
    asm("fma.rn.f32x2 %0, %1, %2, %0;" : "+l"(d) : "l"(a), "l"(b));
}

__global__ __launch_bounds__(THREADS, 1)
void enc_kernel(const float* __restrict__ x, const float* __restrict__ w,
                float* __restrict__ out)
{
    extern __shared__ float sm[];
    const int b = blockIdx.x;
    const int tid = threadIdx.x;

    // ---- P0: eps taps (replicating jnp op sequence) + zero pads ----
    if (tid < 100) {
        float tk = (float)tid / 10.0f;        // fl32(k/10)
        float e  = tk * expf(1.0f - tk);      // libdevice expf == XLA exp, one product rounding
        ((ull*)(sm + OFF_EPS))[tid] = pack2(e, e);
    }
    for (int i = tid; i < NPAIR * PAD2 * 2; i += THREADS) {
        int pr = i / (PAD2 * 2), off = i % (PAD2 * 2);
        sm[OFF_XI2 + pr * XROW2F + off] = 0.0f;
    }

    // ---- P1: per-chunk 100-tap FIR (channel-pair f32x2, ascending k) ----
    const int cpr = tid / CONV_TG;             // 0..12
    const int ctg = tid % CONV_TG;             // 0..18
    const int ct0 = ctg * CONV_TILE;           // even
    const bool cact = (tid < CONV_ACT);
    const ull* e2 = (const ull*)(sm + OFF_EPS);

    for (int cc = 0; cc < NCHUNK; cc++) {
        __syncthreads();
        // load x chunk interleaved by channel pairs
        {
            const float* xb = x + ((size_t)b * CIN + cc * CCHUNK) * TT;
            for (int i = tid; i < CCHUNK * TT; i += THREADS) {
                int cl = i / TT, t = i % TT;
                sm[OFF_XI2 + (cl >> 1) * XROW2F + 2 * (PAD2 + t) + (cl & 1)] = xb[i];
            }
        }
        __syncthreads();

        ull acc2[CONV_TILE];
        #pragma unroll
        for (int j = 0; j < CONV_TILE; j++) acc2[j] = 0ULL;

        if (cact) {
            const float* rowf = sm + OFF_XI2 + cpr * XROW2F;
            ull W[24];
            {   // init window: float2 idx [94+ct0 .. 94+ct0+23]
                const ulonglong2* p = (const ulonglong2*)(rowf + 2 * (94 + ct0));
                #pragma unroll
                for (int m = 0; m < 12; m++) { ulonglong2 v = p[m]; W[2*m] = v.x; W[2*m+1] = v.y; }
            }
            #pragma unroll
            for (int kk = 0; kk < 100; kk += 4) {
                #pragma unroll
                for (int i = 0; i < 4; i++) {
                    ull ek = e2[kk + i];
                    #pragma unroll
                    for (int j = 0; j < CONV_TILE; j++)
                        fma2(acc2[j], ek, W[j - i + 6]);
                }
                if (kk < 96) {
                    #pragma unroll
                    for (int m = 23; m >= 4; m--) W[m] = W[m - 4];
                    const ulonglong2* p = (const ulonglong2*)(rowf + 2 * (90 + ct0 - kk));
                    ulonglong2 v0 = p[0], v1 = p[1];
                    W[0] = v0.x; W[1] = v0.y; W[2] = v1.x; W[3] = v1.y;
                }
            }
        }
        __syncthreads();   // all window reads done before store may hit staging (cc==5)
        if (cact) {
            #pragma unroll
            for (int j = 0; j < CONV_TILE; j++) {
                int t = ct0 + j;
                if (t < TT) {
                    float lo, hi; unpack2(acc2[j], lo, hi);
                    int c0 = cc * CCHUNK + 2 * cpr;
                    sm[OFF_PSP + c0 * TT + t]       = lo;
                    sm[OFF_PSP + (c0 + 1) * TT + t] = hi;
                }
            }
        }
    }

    // ---- P2: GEMM u[o][t] = sum_c w[o][c]*psp[c][t], ascending c ----
    const int og = tid % OG;                  // 0..4
    const int gtg = tid / OG;                 // 0..40
    const int gt0 = gtg * 8;
    const int obase = og * 10;
    const bool gact = (tid < GEMM_ACT);

    ull acc[5][8];
    #pragma unroll
    for (int m = 0; m < 5; m++)
        #pragma unroll
        for (int j = 0; j < 8; j++) acc[m][j] = 0ULL;

    for (int cc = 0; cc < NCHUNK; cc++) {
        __syncthreads();
        for (int i = tid; i < CCHUNK * COUT; i += THREADS) {
            int cl = i / COUT, o = i % COUT;
            sm[OFF_WS + cl * 52 + o] = w[o * CIN + cc * CCHUNK + cl];
        }
        __syncthreads();
        if (gact) {
            #pragma unroll 2
            for (int cl = 0; cl < CCHUNK; cl++) {
                const float* xb = sm + OFF_PSP + (cc * CCHUNK + cl) * TT + gt0;
                ull xp[8];
                #pragma unroll
                for (int j = 0; j < 8; j++) { float xv = xb[j]; xp[j] = pack2(xv, xv); }
                const ull* wrow = (const ull*)(sm + OFF_WS + cl * 52 + obase);
                ull wv[5];
                #pragma unroll
                for (int m = 0; m < 5; m++) wv[m] = wrow[m];
                #pragma unroll
                for (int m = 0; m < 5; m++)
                    #pragma unroll
                    for (int j = 0; j < 8; j++)
                        fma2(acc[m][j], wv[m], xp[j]);
            }
        }
    }

    // ---- P3: write y (psp now dead) ----
    __syncthreads();
    if (gact) {
        #pragma unroll
        for (int m = 0; m < 5; m++)
            #pragma unroll
            for (int j = 0; j < 8; j++) {
                int t = gt0 + j;
                if (t < TT) {
                    float lo, hi; unpack2(acc[m][j], lo, hi);
                    sm[OFF_Y + (obase + 2 * m)     * YSTR + t] = lo;
                    sm[OFF_Y + (obase + 2 * m + 1) * YSTR + t] = hi;
                }
            }
    }
    __syncthreads();

    // ---- P4: exact refractory scan (bit-replicates the jax buffer update) ----
    if (tid < COUT) {
        const float* yrow = sm + OFF_Y + tid * YSTR;
        float* srow = sm + OFF_S + tid * YSTR;

        float nu1[31];   // nu[d], d=1..31, replicating jnp op sequence
        #pragma unroll
        for (int d = 1; d <= 31; d++) {
            float td = (float)d;
            nu1[d - 1] = (-20.0f * td) * expf(1.0f - td);
        }
        float rf[32];
        #pragma unroll
        for (int i = 0; i < 32; i++) rf[i] = 0.0f;

        for (int t = 0; t < TT; t++) {
            float v = yrow[t] + rf[0];
            float s = (v >= 10.0f) ? 1.0f : 0.0f;
            srow[t] = s;
            #pragma unroll
            for (int i = 0; i < 31; i++) rf[i] = fmaf(s, nu1[i], rf[i + 1]);
            rf[31] = 0.0f;
        }
    }
    __syncthreads();

    // ---- P5: coalesced copy-out ----
    float* ob = out + (size_t)b * (COUT * TT);
    for (int i = tid; i < COUT * TT; i += THREADS) {
        int o = i / TT, t = i % TT;
        ob[i] = sm[OFF_S + o * YSTR + t];
    }
}

extern "C" void kernel_launch(void* const* d_in, const int* in_sizes, int n_in,
                              void* d_out, int out_size)
{
    const float* x = (const float*)d_in[0];
    const float* w = (const float*)d_in[1];
    if (n_in >= 2 && in_sizes[0] == COUT * CIN) {   // robustness to input order
        x = (const float*)d_in[1];
        w = (const float*)d_in[0];
    }
    cudaFuncSetAttribute(enc_kernel, cudaFuncAttributeMaxDynamicSharedMemorySize,
                         SMEM_FLOATS * (int)sizeof(float));
    enc_kernel<<<NB, THREADS, SMEM_FLOATS * sizeof(float)>>>(x, w, (float*)d_out);
}

// round 3
// speedup vs baseline: 1.1082x; 1.1082x over previous
#include <cuda_runtime.h>
#include <math.h>

#define NB   512
#define CIN  156
#define COUT 50
#define TT   325
#define THREADS 512

#define CCHUNK 26
#define NCHUNK 6
#define NPAIR  13
#define XROW2F 852          // floats per interleaved pair-row (2*(100 pad + 325) + 2 spare)
#define PAD2   100          // left zero pad, in float2 units

#define CONV_NTG  33
#define CONV_TILE 10
#define CONV_ACT  (NPAIR*CONV_NTG)   // 429

#define OG 5
#define GEMM_TILE 4
#define GEMM_NTG  82
#define GEMM_ACT  (OG*GEMM_NTG)      // 410

// smem float offsets
#define OFF_EPS 0                      // ull eps2[100] = 200 floats
#define OFF_PSP 200                    // psp[156][325]
#define OFF_XI2 42452                  // staging, overlaps psp rows 130..155 (alias handled)
#define XI2_SZ  (NPAIR*XROW2F + 24)    // +24 slack for tail-thread overreads
#define OFF_WS  (OFF_XI2 + XI2_SZ)     // 53576
#define SMEM_FLOATS (OFF_WS + CCHUNK*52)   // 54928 floats = 219,712 B

#define OFF_Y   200                    // y[50][YSTR], overlays dead psp; spikes in-place
#define YSTR    327

typedef unsigned long long ull;

__device__ __forceinline__ ull pack2(float lo, float hi) {
    ull r; asm("mov.b64 %0, {%1, %2};" : "=l"(r) : "f"(lo), "f"(hi)); return r;
}
__device__ __forceinline__ void unpack2(ull v, float &lo, float &hi) {
    asm("mov.b64 {%0, %1}, %2;" : "=f"(lo), "=f"(hi) : "l"(v));
}
__device__ __forceinline__ void fma2(ull &d, ull a, ull b) {
    asm("fma.rn.f32x2 %0, %1, %2, %0;" : "+l"(d) : "l"(a), "l"(b));
}

__global__ __launch_bounds__(THREADS, 1)
void enc_kernel(const float* __restrict__ x, const float* __restrict__ w,
                float* __restrict__ out)
{
    extern __shared__ float sm[];
    const int b = blockIdx.x;
    const int tid = threadIdx.x;

    // ---- P0: eps taps (replicating jnp op sequence) + zero pads ----
    if (tid < 100) {
        float tk = (float)tid / 10.0f;
        float e  = tk * expf(1.0f - tk);
        ((ull*)(sm + OFF_EPS))[tid] = pack2(e, e);
    }
    for (int i = tid; i < NPAIR * PAD2 * 2; i += THREADS) {
        int pr = i / (PAD2 * 2), off = i % (PAD2 * 2);
        sm[OFF_XI2 + pr * XROW2F + off] = 0.0f;
    }

    // ---- P1: per-chunk 100-tap FIR (channel-pair f32x2, ascending k) ----
    const int cpr = tid / CONV_NTG;            // 0..12
    const int ctg = tid % CONV_NTG;            // 0..32
    const int ct0 = ctg * CONV_TILE;           // even
    const bool cact = (tid < CONV_ACT);
    const ull* e2 = (const ull*)(sm + OFF_EPS);

    for (int cc = 0; cc < NCHUNK; cc++) {
        __syncthreads();
        {
            const float* xb = x + ((size_t)b * CIN + cc * CCHUNK) * TT;
            for (int i = tid; i < CCHUNK * TT; i += THREADS) {
                int cl = i / TT, t = i % TT;
                sm[OFF_XI2 + (cl >> 1) * XROW2F + 2 * (PAD2 + t) + (cl & 1)] = xb[i];
            }
        }
        __syncthreads();

        ull acc2[CONV_TILE];
        #pragma unroll
        for (int j = 0; j < CONV_TILE; j++) acc2[j] = 0ULL;

        if (cact) {
            const float* rowf = sm + OFF_XI2 + cpr * XROW2F;
            ull W[16];
            {   // init window: float2 idx [96+ct0 .. 96+ct0+15] (W[14],W[15] dead)
                const ulonglong2* p = (const ulonglong2*)(rowf + 2 * (96 + ct0));
                #pragma unroll
                for (int m = 0; m < 8; m++) { ulonglong2 v = p[m]; W[2*m] = v.x; W[2*m+1] = v.y; }
            }
            #pragma unroll
            for (int kk = 0; kk < 100; kk += 4) {
                #pragma unroll
                for (int i = 0; i < 4; i++) {
                    ull ek = e2[kk + i];
                    #pragma unroll
                    for (int j = 0; j < CONV_TILE; j++)
                        fma2(acc2[j], ek, W[j - i + 4]);
                }
                if (kk < 96) {
                    #pragma unroll
                    for (int m = 15; m >= 4; m--) W[m] = W[m - 4];
                    const ulonglong2* p = (const ulonglong2*)(rowf + 2 * (92 + ct0 - kk));
                    ulonglong2 v0 = p[0], v1 = p[1];
                    W[0] = v0.x; W[1] = v0.y; W[2] = v1.x; W[3] = v1.y;
                }
            }
        }
        __syncthreads();   // all window reads done before stores may alias staging (cc==5)
        if (cact) {
            #pragma unroll
            for (int j = 0; j < CONV_TILE; j++) {
                int t = ct0 + j;
                if (t < TT) {
                    float lo, hi; unpack2(acc2[j], lo, hi);
                    int c0 = cc * CCHUNK + 2 * cpr;
                    sm[OFF_PSP + c0 * TT + t]       = lo;
                    sm[OFF_PSP + (c0 + 1) * TT + t] = hi;
                }
            }
        }
    }

    // ---- P2: GEMM u[o][t] = sum_c w[o][c]*psp[c][t], ascending c ----
    const int og = tid % OG;                  // 0..4
    const int gtg = tid / OG;                 // 0..101
    const int gt0 = gtg * GEMM_TILE;
    const int obase = og * 10;
    const bool gact = (tid < GEMM_ACT);

    ull acc[5][GEMM_TILE];
    #pragma unroll
    for (int m = 0; m < 5; m++)
        #pragma unroll
        for (int j = 0; j < GEMM_TILE; j++) acc[m][j] = 0ULL;

    for (int cc = 0; cc < NCHUNK; cc++) {
        __syncthreads();
        for (int i = tid; i < CCHUNK * COUT; i += THREADS) {
            int cl = i / COUT, o = i % COUT;
            sm[OFF_WS + cl * 52 + o] = w[o * CIN + cc * CCHUNK + cl];
        }
        __syncthreads();
        if (gact) {
            #pragma unroll 2
            for (int cl = 0; cl < CCHUNK; cl++) {
                const float* xb = sm + OFF_PSP + (cc * CCHUNK + cl) * TT + gt0;
                ull xp[GEMM_TILE];
                #pragma unroll
                for (int j = 0; j < GEMM_TILE; j++) { float xv = xb[j]; xp[j] = pack2(xv, xv); }
                const ull* wrow = (const ull*)(sm + OFF_WS + cl * 52 + obase);
                ull wv[5];
                #pragma unroll
                for (int m = 0; m < 5; m++) wv[m] = wrow[m];
                #pragma unroll
                for (int m = 0; m < 5; m++)
                    #pragma unroll
                    for (int j = 0; j < GEMM_TILE; j++)
                        fma2(acc[m][j], wv[m], xp[j]);
            }
        }
    }

    // ---- P3: write y (psp now dead) ----
    __syncthreads();
    if (gact) {
        #pragma unroll
        for (int m = 0; m < 5; m++)
            #pragma unroll
            for (int j = 0; j < GEMM_TILE; j++) {
                int t = gt0 + j;
                if (t < TT) {
                    float lo, hi; unpack2(acc[m][j], lo, hi);
                    sm[OFF_Y + (obase + 2 * m)     * YSTR + t] = lo;
                    sm[OFF_Y + (obase + 2 * m + 1) * YSTR + t] = hi;
                }
            }
    }
    __syncthreads();

    // ---- P4: exact refractory scan (bit-replicates the jax buffer update), in-place ----
    if (tid < COUT) {
        float* yrow = sm + OFF_Y + tid * YSTR;

        float nu1[31];
        #pragma unroll
        for (int d = 1; d <= 31; d++) {
            float td = (float)d;
            nu1[d - 1] = (-20.0f * td) * expf(1.0f - td);
        }
        float rf[32];
        #pragma unroll
        for (int i = 0; i < 32; i++) rf[i] = 0.0f;

        for (int t = 0; t < TT; t++) {
            float v = yrow[t] + rf[0];
            float s = (v >= 10.0f) ? 1.0f : 0.0f;
            yrow[t] = s;
            #pragma unroll
            for (int i = 0; i < 31; i++) rf[i] = fmaf(s, nu1[i], rf[i + 1]);
            rf[31] = 0.0f;
        }
    }
    __syncthreads();

    // ---- P5: coalesced copy-out ----
    float* ob = out + (size_t)b * (COUT * TT);
    for (int i = tid; i < COUT * TT; i += THREADS) {
        int o = i / TT, t = i % TT;
        ob[i] = sm[OFF_Y + o * YSTR + t];
    }
}

extern "C" void kernel_launch(void* const* d_in, const int* in_sizes, int n_in,
                              void* d_out, int out_size)
{
    const float* x = (const float*)d_in[0];
    const float* w = (const float*)d_in[1];
    if (n_in >= 2 && in_sizes[0] == COUT * CIN) {
        x = (const float*)d_in[1];
        w = (const float*)d_in[0];
    }
    cudaFuncSetAttribute(enc_kernel, cudaFuncAttributeMaxDynamicSharedMemorySize,
                         SMEM_FLOATS * (int)sizeof(float));
    enc_kernel<<<NB, THREADS, SMEM_FLOATS * sizeof(float)>>>(x, w, (float*)d_out);
}